// round 14
// baseline (speedup 1.0000x reference)
#include <cuda_runtime.h>

#define NNODES 200000
#define INDIM  128
#define H1     256
#define HID    16
#define NEG    0.01f
#define EMAX   6400000
#define CAP    128           // bucket capacity per node (deg ~Poisson(32); P(>128) ~ 1e-40)

// ---------------- scratch (device globals; no runtime allocation) ----------------
__device__ float g_h   [NNODES * HID];   // MLP output
__device__ float g_hw  [NNODES * HID];   // (h @ cw) * dinv  (per conv layer)
__device__ float g_agg [NNODES * HID];   // aggregation result (conv0)
__device__ int   g_cnt [NNODES];         // in-degree (no self loop) / scatter cursor
__device__ int   g_srcs[NNODES * CAP];   // bucketed CSR: src nodes per dst

__device__ __forceinline__ float lrelu(float v) { return v >= 0.f ? v : NEG * v; }

__device__ __forceinline__ int clampN(int i)
{
    i = i < 0 ? 0 : i;
    return i >= NNODES ? NNODES - 1 : i;
}

// ---- tf32 helpers -------------------------------------------------------------
__device__ __forceinline__ void split_tf32(float v, unsigned& hi, unsigned& lo)
{
    asm("cvt.rna.tf32.f32 %0, %1;" : "=r"(hi) : "f"(v));
    float r = v - __uint_as_float(hi);
    asm("cvt.rna.tf32.f32 %0, %1;" : "=r"(lo) : "f"(r));
}

#define MMA_TF32(d, a, b)                                                        \
    asm("mma.sync.aligned.m16n8k8.row.col.f32.tf32.tf32.f32 "                    \
        "{%0,%1,%2,%3},{%4,%5,%6,%7},{%8,%9},{%0,%1,%2,%3};"                     \
        : "+f"((d)[0]), "+f"((d)[1]), "+f"((d)[2]), "+f"((d)[3])                 \
        : "r"((a)[0]), "r"((a)[1]), "r"((a)[2]), "r"((a)[3]),                    \
          "r"((b)[0]), "r"((b)[1]))

// ---------------- fused tensor-core MLP — B-splits hoisted to stage time ---------
// smem (floats):
//  stage A: xs @0 (64x132=8448) | whi @8448 (32x264=8448) | wlo @16896 (8448)
//  stage B: h1s @0 (64x260=16640) | w2s @16640 (256x24=6144)  [loaded after stage A]
#define XS  132
#define WS  264
#define HS  260
#define W2S 24
#define SMEM_FLOATS 25344

__global__ __launch_bounds__(256) void mlp_tc_kernel(
    const float* __restrict__ x,
    const float* __restrict__ W1, const float* __restrict__ b1,
    const float* __restrict__ W2, const float* __restrict__ b2)
{
    extern __shared__ float sm[];
    float* xs  = sm;
    float* whi = sm + 8448;
    float* wlo = sm + 16896;
    float* h1s = sm;
    float* w2s = sm + 16640;

    const int tid  = threadIdx.x;
    const int wid  = tid >> 5;
    const int lane = tid & 31;
    const int g    = lane >> 2;
    const int t    = lane & 3;
    const int n0   = blockIdx.x * 64;

    {
        const float4* xg = (const float4*)(x + (size_t)n0 * INDIM);
        #pragma unroll
        for (int i = 0; i < 8; i++) {
            int lin = i * 256 + tid;
            int row = lin >> 5, c4 = (lin & 31) << 2;
            float4 v = xg[lin];
            *(float4*)(xs + row * XS + c4) = v;
        }
    }

    const int wm = wid >> 2;
    const int wn = wid & 3;
    float acc[2][8][4];
    #pragma unroll
    for (int mt = 0; mt < 2; mt++)
        #pragma unroll
        for (int nt = 0; nt < 8; nt++)
            #pragma unroll
            for (int r = 0; r < 4; r++) acc[mt][nt][r] = 0.f;

    for (int k0 = 0; k0 < INDIM; k0 += 32) {
        __syncthreads();
        {
            // stage W1 chunk [32][256], pre-split into tf32 hi/lo (once per chunk)
            const float4* wg = (const float4*)(W1 + (size_t)k0 * H1);
            #pragma unroll
            for (int i = 0; i < 8; i++) {
                int lin = i * 256 + tid;
                int row = lin >> 6, c4 = (lin & 63) << 2;
                float4 v = wg[lin];
                unsigned h0,l0,h1,l1,h2,l2,h3,l3;
                split_tf32(v.x, h0, l0);
                split_tf32(v.y, h1, l1);
                split_tf32(v.z, h2, l2);
                split_tf32(v.w, h3, l3);
                *(float4*)(whi + row * WS + c4) = make_float4(
                    __uint_as_float(h0), __uint_as_float(h1),
                    __uint_as_float(h2), __uint_as_float(h3));
                *(float4*)(wlo + row * WS + c4) = make_float4(
                    __uint_as_float(l0), __uint_as_float(l1),
                    __uint_as_float(l2), __uint_as_float(l3));
            }
        }
        __syncthreads();

        #pragma unroll
        for (int ks = 0; ks < 32; ks += 8) {
            unsigned ahi[2][4], alo[2][4];
            #pragma unroll
            for (int mt = 0; mt < 2; mt++) {
                int rb = wm * 32 + mt * 16;
                float a0 = xs[(rb + g)     * XS + k0 + ks + t];
                float a1 = xs[(rb + g + 8) * XS + k0 + ks + t];
                float a2 = xs[(rb + g)     * XS + k0 + ks + t + 4];
                float a3 = xs[(rb + g + 8) * XS + k0 + ks + t + 4];
                split_tf32(a0, ahi[mt][0], alo[mt][0]);
                split_tf32(a1, ahi[mt][1], alo[mt][1]);
                split_tf32(a2, ahi[mt][2], alo[mt][2]);
                split_tf32(a3, ahi[mt][3], alo[mt][3]);
            }
            #pragma unroll
            for (int nt = 0; nt < 8; nt++) {
                int cb = wn * 64 + nt * 8;
                unsigned bhi[2], blo[2];
                bhi[0] = __float_as_uint(whi[(ks + t)     * WS + cb + g]);
                bhi[1] = __float_as_uint(whi[(ks + t + 4) * WS + cb + g]);
                blo[0] = __float_as_uint(wlo[(ks + t)     * WS + cb + g]);
                blo[1] = __float_as_uint(wlo[(ks + t + 4) * WS + cb + g]);
                #pragma unroll
                for (int mt = 0; mt < 2; mt++) {
                    MMA_TF32(acc[mt][nt], ahi[mt], bhi);
                    MMA_TF32(acc[mt][nt], ahi[mt], blo);
                    MMA_TF32(acc[mt][nt], alo[mt], bhi);
                }
            }
        }
    }
    __syncthreads();

    // epilogue A -> h1s; load w2s (disjoint region, after stage A reads done)
    #pragma unroll
    for (int mt = 0; mt < 2; mt++) {
        int rb = wm * 32 + mt * 16;
        #pragma unroll
        for (int nt = 0; nt < 8; nt++) {
            int cb = wn * 64 + nt * 8 + t * 2;
            float bb0 = b1[cb], bb1 = b1[cb + 1];
            h1s[(rb + g)     * HS + cb    ] = lrelu(acc[mt][nt][0] + bb0);
            h1s[(rb + g)     * HS + cb + 1] = lrelu(acc[mt][nt][1] + bb1);
            h1s[(rb + g + 8) * HS + cb    ] = lrelu(acc[mt][nt][2] + bb0);
            h1s[(rb + g + 8) * HS + cb + 1] = lrelu(acc[mt][nt][3] + bb1);
        }
    }
    {
        const float4* wg = (const float4*)W2;
        #pragma unroll
        for (int i = 0; i < 4; i++) {
            int lin = i * 256 + tid;
            int row = lin >> 2, c4 = (lin & 3) << 2;
            float4 v = wg[lin];
            *(float4*)(w2s + row * W2S + c4) = v;
        }
    }
    __syncthreads();

    {
        const int mt2 = wid >> 1;
        const int nt2 = wid & 1;
        const int rb  = mt2 * 16;
        const int cb  = nt2 * 8;
        float d[4] = {0.f, 0.f, 0.f, 0.f};

        #pragma unroll 4
        for (int k = 0; k < H1; k += 8) {
            float a0 = h1s[(rb + g)     * HS + k + t];
            float a1 = h1s[(rb + g + 8) * HS + k + t];
            float a2 = h1s[(rb + g)     * HS + k + t + 4];
            float a3 = h1s[(rb + g + 8) * HS + k + t + 4];
            unsigned ahi[4], alo[4];
            split_tf32(a0, ahi[0], alo[0]);
            split_tf32(a1, ahi[1], alo[1]);
            split_tf32(a2, ahi[2], alo[2]);
            split_tf32(a3, ahi[3], alo[3]);
            float b0f = w2s[(k + t)     * W2S + cb + g];
            float b1f = w2s[(k + t + 4) * W2S + cb + g];
            unsigned bhi[2], blo[2];
            split_tf32(b0f, bhi[0], blo[0]);
            split_tf32(b1f, bhi[1], blo[1]);
            MMA_TF32(d, ahi, bhi);
            MMA_TF32(d, ahi, blo);
            MMA_TF32(d, alo, bhi);
        }

        int col = cb + t * 2;
        float bb0 = b2[col], bb1 = b2[col + 1];
        g_h[(size_t)(n0 + rb + g)     * HID + col    ] = lrelu(d[0] + bb0);
        g_h[(size_t)(n0 + rb + g)     * HID + col + 1] = lrelu(d[1] + bb1);
        g_h[(size_t)(n0 + rb + g + 8) * HID + col    ] = lrelu(d[2] + bb0);
        g_h[(size_t)(n0 + rb + g + 8) * HID + col + 1] = lrelu(d[3] + bb1);
    }
}

// ---------------- bucket CSR build (no scans) -----------------------------------
__global__ void zero_cnt_kernel(int base)
{
    int i = base + blockIdx.x * blockDim.x + threadIdx.x;
    if (i < NNODES) g_cnt[i] = 0;
}

__global__ void scatter_kernel(const int* __restrict__ src, const int* __restrict__ dst, int E)
{
    int e = blockIdx.x * blockDim.x + threadIdx.x;
    if (e >= E) return;
    const int s = clampN(src[e]);
    const int d = clampN(dst[e]);
    int pos = atomicAdd(&g_cnt[d], 1);
    if (pos < CAP) g_srcs[d * CAP + pos] = s;
}

// ---------------- per-conv: g_hw = ((maybe lrelu)(in) @ cw) * dinv --------------
__global__ __launch_bounds__(256) void conv_pre_kernel(
    int src_sel,
    const float* __restrict__ cw)
{
    __shared__ float ws[HID * HID];
    __shared__ float ht[16 * HID];

    const int tid = threadIdx.x;
    const int n0  = blockIdx.x * 16;

    if (tid < HID * HID) ws[tid] = cw[tid];
    {
        float v;
        if (src_sel == 0) v = g_h[n0 * HID + tid];
        else              v = lrelu(g_agg[n0 * HID + tid]);
        ht[tid] = v;
    }
    __syncthreads();

    const int n = tid >> 4, j = tid & 15;
    float s = 0.f;
    #pragma unroll
    for (int k = 0; k < HID; k++) s += ht[n * HID + k] * ws[k * HID + j];

    const int gn = n0 + n;
    const float di = rsqrtf((float)(g_cnt[gn] + 1));   // +1 self loop
    g_hw[gn * HID + j] = s * di;
}

// ---------------- aggregation: warp per node, direct-index bucket gather --------
__global__ __launch_bounds__(256) void agg_kernel(
    const float* __restrict__ cb,
    const float* __restrict__ pw, const float* __restrict__ pb,
    float* __restrict__ out, long long out_size, int last)
{
    const int wid  = threadIdx.x >> 5;
    const int lane = threadIdx.x & 31;
    const int n    = blockIdx.x * 8 + wid;   // grid exact: 25000*8

    const int q  = lane & 3;       // feature quad
    const int es = lane >> 2;      // edge sub-slot 0..7

    int cnt = g_cnt[n];
    if (cnt > CAP) cnt = CAP;
    const int beg = n * CAP;
    const int end = beg + cnt;

    float4 acc = make_float4(0.f, 0.f, 0.f, 0.f);

    for (int i = beg + es; i < end; i += 8) {
        const int s = g_srcs[i];
        const float4 v = *(const float4*)(g_hw + (size_t)s * HID + q * 4);
        acc.x += v.x; acc.y += v.y; acc.z += v.z; acc.w += v.w;
    }

    #pragma unroll
    for (int o = 16; o >= 4; o >>= 1) {
        acc.x += __shfl_xor_sync(0xffffffffu, acc.x, o);
        acc.y += __shfl_xor_sync(0xffffffffu, acc.y, o);
        acc.z += __shfl_xor_sync(0xffffffffu, acc.z, o);
        acc.w += __shfl_xor_sync(0xffffffffu, acc.w, o);
    }

    if (lane < 4) {
        const float4 hwn = *(const float4*)(g_hw + (size_t)n * HID + q * 4);
        const float  di  = rsqrtf((float)(cnt + 1));
        const float4 cb4 = __ldg((const float4*)cb + q);
        float r0 = cb4.x + di * (acc.x + hwn.x);
        float r1 = cb4.y + di * (acc.y + hwn.y);
        float r2 = cb4.z + di * (acc.z + hwn.z);
        float r3 = cb4.w + di * (acc.w + hwn.w);

        if (!last) {
            *(float4*)(g_agg + (size_t)n * HID + q * 4) =
                make_float4(r0, r1, r2, r3);
        } else {
            float h0 = lrelu(r0), h1 = lrelu(r1), h2 = lrelu(r2), h3 = lrelu(r3);
            if (out_size >= (long long)NNODES * (1 + HID))
                *(float4*)(out + NNODES + (size_t)n * HID + q * 4) =
                    make_float4(h0, h1, h2, h3);

            const float4 pwa = __ldg((const float4*)pw + q * 2);
            const float4 pwb = __ldg((const float4*)pw + q * 2 + 1);
            float part = h0 * (pwa.x + pwa.y) + h1 * (pwa.z + pwa.w)
                       + h2 * (pwb.x + pwb.y) + h3 * (pwb.z + pwb.w);
            part += __shfl_xor_sync(0x0000000fu, part, 1);
            part += __shfl_xor_sync(0x0000000fu, part, 2);
            if (q == 0) out[n] = part + pb[0] + pb[1];
        }
    }
}

// ---------------- launch: fork-join across two streams ---------------------------
extern "C" void kernel_launch(void* const* d_in, const int* in_sizes, int n_in,
                              void* d_out, int out_size)
{
    const float *x = 0, *W1 = 0, *b1 = 0, *W2 = 0, *b2 = 0;
    const float *cw0 = 0, *cb0 = 0, *cw1 = 0, *cb1 = 0, *pw = 0, *pb = 0;
    const void  *edges = 0;
    long long    edge_elems = 0;

    int n256 = 0, n16 = 0;
    for (int i = 0; i < n_in; i++) {
        const long long sz = in_sizes[i];
        const void* p = d_in[i];
        switch (sz) {
            case 25600000LL: x  = (const float*)p; break;
            case 32768LL:    W1 = (const float*)p; break;
            case 4096LL:     W2 = (const float*)p; break;
            case 32LL:       pw = (const float*)p; break;
            case 2LL:        pb = (const float*)p; break;
            case 256LL:
                if      (n256 == 0) b1  = (const float*)p;
                else if (n256 == 1) cw0 = (const float*)p;
                else                cw1 = (const float*)p;
                n256++; break;
            case 16LL:
                if      (n16 == 0) b2  = (const float*)p;
                else if (n16 == 1) cb0 = (const float*)p;
                else               cb1 = (const float*)p;
                n16++; break;
            default:
                if (sz > 1000000LL) { edges = p; edge_elems = sz; }
                break;
        }
    }

    int E = (int)(edge_elems / 2);
    if (E > EMAX) E = EMAX;
    const int* srcp = (const int*)edges;
    const int* dstp = (const int*)edges + E;

    float* out = (float*)d_out;

    const int NB_NODES16 = NNODES / 16;
    const int HALF       = NNODES / 2;
    const int NB_HALF    = (HALF + 255) / 256;
    const int NB_EDGES   = (E + 255) / 256;
    const int NB_AGG     = NNODES / 8;   // 25000 exact

    static int inited = 0;
    static cudaStream_t s2 = 0;
    static cudaEvent_t  evRoot = 0, evCsr = 0;
    if (!inited) {
        cudaFuncSetAttribute(mlp_tc_kernel,
                             cudaFuncAttributeMaxDynamicSharedMemorySize,
                             SMEM_FLOATS * 4);
        cudaStreamCreateWithFlags(&s2, cudaStreamNonBlocking);
        cudaEventCreateWithFlags(&evRoot, cudaEventDisableTiming);
        cudaEventCreateWithFlags(&evCsr,  cudaEventDisableTiming);
        inited = 1;
    }

    // fork: s2 builds the bucket CSR while stream0 runs the MLP
    cudaEventRecord(evRoot, 0);
    cudaStreamWaitEvent(s2, evRoot, 0);

    zero_cnt_kernel<<<NB_HALF, 256, 0, s2>>>(0);
    zero_cnt_kernel<<<NB_HALF, 256, 0, s2>>>(HALF);
    scatter_kernel <<<NB_EDGES, 256, 0, s2>>>(srcp, dstp, E);
    cudaEventRecord(evCsr, s2);

    mlp_tc_kernel<<<NNODES / 64, 256, SMEM_FLOATS * 4>>>(x, W1, b1, W2, b2);   // launch 4

    cudaStreamWaitEvent(0, evCsr, 0);
    conv_pre_kernel<<<NB_NODES16, 256>>>(0, cw0);                               // launch 5
    agg_kernel<<<NB_AGG, 256>>>(cb0, pw, pb, out, (long long)out_size, 0);      // launch 6 (ncu)

    conv_pre_kernel<<<NB_NODES16, 256>>>(1, cw1);
    agg_kernel<<<NB_AGG, 256>>>(cb1, pw, pb, out, (long long)out_size, 1);
}

// round 15
// speedup vs baseline: 1.2636x; 1.2636x over previous
#include <cuda_runtime.h>
#include <cuda_bf16.h>

#define NNODES 200000
#define INDIM  128
#define H1     256
#define HID    16
#define NEG    0.01f
#define EMAX   6400000
#define CAP    128           // bucket capacity per node (deg ~Poisson(32); P(>128) ~ 1e-40)

// ---------------- scratch (device globals; no runtime allocation) ----------------
__device__ float g_h   [NNODES * HID];   // MLP output
__device__ float g_hw  [NNODES * HID];   // (h @ cw) * dinv  (per conv layer)
__device__ float g_agg [NNODES * HID];   // aggregation result (conv0)
__device__ int   g_cnt [NNODES];         // in-degree (no self loop) / scatter cursor
__device__ int   g_srcs[NNODES * CAP];   // bucketed CSR: src nodes per dst

__device__ __forceinline__ float lrelu(float v) { return v >= 0.f ? v : NEG * v; }

__device__ __forceinline__ int clampN(int i)
{
    i = i < 0 ? 0 : i;
    return i >= NNODES ? NNODES - 1 : i;
}

// ---- tf32 helpers (stage B only) ----------------------------------------------
__device__ __forceinline__ void split_tf32(float v, unsigned& hi, unsigned& lo)
{
    asm("cvt.rna.tf32.f32 %0, %1;" : "=r"(hi) : "f"(v));
    float r = v - __uint_as_float(hi);
    asm("cvt.rna.tf32.f32 %0, %1;" : "=r"(lo) : "f"(r));
}

#define MMA_TF32(d, a, b)                                                        \
    asm("mma.sync.aligned.m16n8k8.row.col.f32.tf32.tf32.f32 "                    \
        "{%0,%1,%2,%3},{%4,%5,%6,%7},{%8,%9},{%0,%1,%2,%3};"                     \
        : "+f"((d)[0]), "+f"((d)[1]), "+f"((d)[2]), "+f"((d)[3])                 \
        : "r"((a)[0]), "r"((a)[1]), "r"((a)[2]), "r"((a)[3]),                    \
          "r"((b)[0]), "r"((b)[1]))

// ---- bf16 helpers (stage A) -----------------------------------------------------
#define MMA_BF16(d, a, b)                                                        \
    asm("mma.sync.aligned.m16n8k16.row.col.f32.bf16.bf16.f32 "                   \
        "{%0,%1,%2,%3},{%4,%5,%6,%7},{%8,%9},{%0,%1,%2,%3};"                     \
        : "+f"((d)[0]), "+f"((d)[1]), "+f"((d)[2]), "+f"((d)[3])                 \
        : "r"((a)[0]), "r"((a)[1]), "r"((a)[2]), "r"((a)[3]),                    \
          "r"((b)[0]), "r"((b)[1]))

// split f0,f1 into bf16 hi + bf16 residual-lo, packed (f0 low half, f1 high half)
__device__ __forceinline__ void split2_pack(float f0, float f1, unsigned& hp, unsigned& lp)
{
    __nv_bfloat16 h0 = __float2bfloat16(f0);
    __nv_bfloat16 h1 = __float2bfloat16(f1);
    float r0 = f0 - __bfloat162float(h0);
    float r1 = f1 - __bfloat162float(h1);
    __nv_bfloat16 l0 = __float2bfloat16(r0);
    __nv_bfloat16 l1 = __float2bfloat16(r1);
    hp = (unsigned)__bfloat16_as_ushort(h0) | ((unsigned)__bfloat16_as_ushort(h1) << 16);
    lp = (unsigned)__bfloat16_as_ushort(l0) | ((unsigned)__bfloat16_as_ushort(l1) << 16);
}

// ---------------- fused MLP: stage A = 3x-split-bf16 mma, stage B = 3xTF32 -------
// smem (4B units):
//  stage A: xhi @0 (64x68=4352) | xlo @4352 | whi @8704 (16x264=4224) | wlo @12928
//  stage B: h1s @0 (64x260=16640 floats) | w2s @17152 (256x24=6144)
#define XP  68     // uint pitch of packed x rows (64 kpairs used)
#define WP  264    // uint pitch of packed W chunk rows (256 cols used)
#define HS  260
#define W2S 24
#define SMEM_FLOATS 23296

__global__ __launch_bounds__(256) void mlp_tc_kernel(
    const float* __restrict__ x,
    const float* __restrict__ W1, const float* __restrict__ b1,
    const float* __restrict__ W2, const float* __restrict__ b2)
{
    extern __shared__ float sm[];
    unsigned* xhi = (unsigned*)sm;
    unsigned* xlo = (unsigned*)sm + 4352;
    unsigned* whi = (unsigned*)sm + 8704;
    unsigned* wlo = (unsigned*)sm + 12928;
    float*    h1s = sm;
    float*    w2s = sm + 17152;

    const int tid  = threadIdx.x;
    const int wid  = tid >> 5;
    const int lane = tid & 31;
    const int g    = lane >> 2;
    const int t    = lane & 3;
    const int n0   = blockIdx.x * 64;

    // ---- stage x: split+pack to bf16 hi/lo pairs (once) ----
    {
        const float4* xg = (const float4*)(x + (size_t)n0 * INDIM);
        #pragma unroll
        for (int i = 0; i < 8; i++) {
            int lin = i * 256 + tid;              // 2048 float4s
            int row = lin >> 5;
            int kp  = (lin & 31) << 1;            // kpair base (2 per float4)
            float4 v = xg[lin];
            unsigned h0, l0, h1, l1;
            split2_pack(v.x, v.y, h0, l0);
            split2_pack(v.z, v.w, h1, l1);
            *(uint2*)(xhi + row * XP + kp) = make_uint2(h0, h1);
            *(uint2*)(xlo + row * XP + kp) = make_uint2(l0, l1);
        }
    }

    const int wm = wid >> 2;
    const int wn = wid & 3;
    float acc[2][8][4];
    #pragma unroll
    for (int mt = 0; mt < 2; mt++)
        #pragma unroll
        for (int nt = 0; nt < 8; nt++)
            #pragma unroll
            for (int r = 0; r < 4; r++) acc[mt][nt][r] = 0.f;

    // ---- stage A mainloop: 4 chunks of K=32 (16 kpairs) ----
    for (int chunk = 0; chunk < 4; chunk++) {
        const int k0 = chunk * 32;
        __syncthreads();
        {
            // stage W1 chunk [32][256] -> packed bf16 hi/lo [16 kpairs][256]
            #pragma unroll
            for (int i = 0; i < 4; i++) {
                int lin = i * 256 + tid;          // 1024 tasks
                int kp  = lin >> 6;               // 0..15
                int c   = (lin & 63) << 2;        // col base
                const float4 r0 = *(const float4*)(W1 + (size_t)(k0 + 2*kp)     * H1 + c);
                const float4 r1 = *(const float4*)(W1 + (size_t)(k0 + 2*kp + 1) * H1 + c);
                unsigned h0,l0,h1,l1,h2,l2,h3,l3;
                split2_pack(r0.x, r1.x, h0, l0);
                split2_pack(r0.y, r1.y, h1, l1);
                split2_pack(r0.z, r1.z, h2, l2);
                split2_pack(r0.w, r1.w, h3, l3);
                *(uint4*)(whi + kp * WP + c) = make_uint4(h0, h1, h2, h3);
                *(uint4*)(wlo + kp * WP + c) = make_uint4(l0, l1, l2, l3);
            }
        }
        __syncthreads();

        #pragma unroll
        for (int s = 0; s < 2; s++) {             // 2 ksteps of K=16
            const int kpA = (k0 >> 1) + s * 8;    // global kpair base for A
            const int kpB = s * 8;                // chunk-local kpair base for B
            unsigned ahi[2][4], alo[2][4];
            #pragma unroll
            for (int mt = 0; mt < 2; mt++) {
                int rb = wm * 32 + mt * 16;
                ahi[mt][0] = xhi[(rb + g)     * XP + kpA + t];
                ahi[mt][1] = xhi[(rb + g + 8) * XP + kpA + t];
                ahi[mt][2] = xhi[(rb + g)     * XP + kpA + t + 4];
                ahi[mt][3] = xhi[(rb + g + 8) * XP + kpA + t + 4];
                alo[mt][0] = xlo[(rb + g)     * XP + kpA + t];
                alo[mt][1] = xlo[(rb + g + 8) * XP + kpA + t];
                alo[mt][2] = xlo[(rb + g)     * XP + kpA + t + 4];
                alo[mt][3] = xlo[(rb + g + 8) * XP + kpA + t + 4];
            }
            #pragma unroll
            for (int nt = 0; nt < 8; nt++) {
                int cb = wn * 64 + nt * 8;
                unsigned bh[2], bl[2];
                bh[0] = whi[(kpB + t)     * WP + cb + g];
                bh[1] = whi[(kpB + t + 4) * WP + cb + g];
                bl[0] = wlo[(kpB + t)     * WP + cb + g];
                bl[1] = wlo[(kpB + t + 4) * WP + cb + g];
                #pragma unroll
                for (int mt = 0; mt < 2; mt++) {
                    MMA_BF16(acc[mt][nt], ahi[mt], bh);
                    MMA_BF16(acc[mt][nt], ahi[mt], bl);
                    MMA_BF16(acc[mt][nt], alo[mt], bh);
                }
            }
        }
    }
    __syncthreads();   // all stage-A smem reads done; safe to overlay h1s

    // ---- epilogue A -> h1s; load w2s (disjoint region) ----
    #pragma unroll
    for (int mt = 0; mt < 2; mt++) {
        int rb = wm * 32 + mt * 16;
        #pragma unroll
        for (int nt = 0; nt < 8; nt++) {
            int cb = wn * 64 + nt * 8 + t * 2;
            float bb0 = b1[cb], bb1 = b1[cb + 1];
            h1s[(rb + g)     * HS + cb    ] = lrelu(acc[mt][nt][0] + bb0);
            h1s[(rb + g)     * HS + cb + 1] = lrelu(acc[mt][nt][1] + bb1);
            h1s[(rb + g + 8) * HS + cb    ] = lrelu(acc[mt][nt][2] + bb0);
            h1s[(rb + g + 8) * HS + cb + 1] = lrelu(acc[mt][nt][3] + bb1);
        }
    }
    {
        const float4* wg = (const float4*)W2;
        #pragma unroll
        for (int i = 0; i < 4; i++) {
            int lin = i * 256 + tid;
            int row = lin >> 2, c4 = (lin & 3) << 2;
            float4 v = wg[lin];
            *(float4*)(w2s + row * W2S + c4) = v;
        }
    }
    __syncthreads();

    // ---- stage B: 3xTF32, K=256 ----
    {
        const int mt2 = wid >> 1;
        const int nt2 = wid & 1;
        const int rb  = mt2 * 16;
        const int cb  = nt2 * 8;
        float d[4] = {0.f, 0.f, 0.f, 0.f};

        #pragma unroll 4
        for (int k = 0; k < H1; k += 8) {
            float a0 = h1s[(rb + g)     * HS + k + t];
            float a1 = h1s[(rb + g + 8) * HS + k + t];
            float a2 = h1s[(rb + g)     * HS + k + t + 4];
            float a3 = h1s[(rb + g + 8) * HS + k + t + 4];
            unsigned ahi[4], alo[4];
            split_tf32(a0, ahi[0], alo[0]);
            split_tf32(a1, ahi[1], alo[1]);
            split_tf32(a2, ahi[2], alo[2]);
            split_tf32(a3, ahi[3], alo[3]);
            float b0f = w2s[(k + t)     * W2S + cb + g];
            float b1f = w2s[(k + t + 4) * W2S + cb + g];
            unsigned bhi[2], blo[2];
            split_tf32(b0f, bhi[0], blo[0]);
            split_tf32(b1f, bhi[1], blo[1]);
            MMA_TF32(d, ahi, bhi);
            MMA_TF32(d, ahi, blo);
            MMA_TF32(d, alo, bhi);
        }

        int col = cb + t * 2;
        float bb0 = b2[col], bb1 = b2[col + 1];
        g_h[(size_t)(n0 + rb + g)     * HID + col    ] = lrelu(d[0] + bb0);
        g_h[(size_t)(n0 + rb + g)     * HID + col + 1] = lrelu(d[1] + bb1);
        g_h[(size_t)(n0 + rb + g + 8) * HID + col    ] = lrelu(d[2] + bb0);
        g_h[(size_t)(n0 + rb + g + 8) * HID + col + 1] = lrelu(d[3] + bb1);
    }
}

// ---------------- bucket CSR build (no scans) -----------------------------------
__global__ void zero_cnt_kernel(int base)
{
    int i = base + blockIdx.x * blockDim.x + threadIdx.x;
    if (i < NNODES) g_cnt[i] = 0;
}

__global__ void scatter_kernel(const int* __restrict__ src, const int* __restrict__ dst, int E)
{
    int e = blockIdx.x * blockDim.x + threadIdx.x;
    if (e >= E) return;
    const int s = clampN(src[e]);
    const int d = clampN(dst[e]);
    int pos = atomicAdd(&g_cnt[d], 1);
    if (pos < CAP) g_srcs[d * CAP + pos] = s;
}

// ---------------- per-conv: g_hw = ((maybe lrelu)(in) @ cw) * dinv --------------
__global__ __launch_bounds__(256) void conv_pre_kernel(
    int src_sel,
    const float* __restrict__ cw)
{
    __shared__ float ws[HID * HID];
    __shared__ float ht[16 * HID];

    const int tid = threadIdx.x;
    const int n0  = blockIdx.x * 16;

    if (tid < HID * HID) ws[tid] = cw[tid];
    {
        float v;
        if (src_sel == 0) v = g_h[n0 * HID + tid];
        else              v = lrelu(g_agg[n0 * HID + tid]);
        ht[tid] = v;
    }
    __syncthreads();

    const int n = tid >> 4, j = tid & 15;
    float s = 0.f;
    #pragma unroll
    for (int k = 0; k < HID; k++) s += ht[n * HID + k] * ws[k * HID + j];

    const int gn = n0 + n;
    const float di = rsqrtf((float)(g_cnt[gn] + 1));   // +1 self loop
    g_hw[gn * HID + j] = s * di;
}

// ---------------- aggregation: warp per node, direct-index bucket gather --------
__global__ __launch_bounds__(256) void agg_kernel(
    const float* __restrict__ cb,
    const float* __restrict__ pw, const float* __restrict__ pb,
    float* __restrict__ out, long long out_size, int last)
{
    const int wid  = threadIdx.x >> 5;
    const int lane = threadIdx.x & 31;
    const int n    = blockIdx.x * 8 + wid;   // grid exact: 25000*8

    const int q  = lane & 3;       // feature quad
    const int es = lane >> 2;      // edge sub-slot 0..7

    int cnt = g_cnt[n];
    if (cnt > CAP) cnt = CAP;
    const int beg = n * CAP;
    const int end = beg + cnt;

    float4 acc = make_float4(0.f, 0.f, 0.f, 0.f);

    for (int i = beg + es; i < end; i += 8) {
        const int s = g_srcs[i];
        const float4 v = *(const float4*)(g_hw + (size_t)s * HID + q * 4);
        acc.x += v.x; acc.y += v.y; acc.z += v.z; acc.w += v.w;
    }

    #pragma unroll
    for (int o = 16; o >= 4; o >>= 1) {
        acc.x += __shfl_xor_sync(0xffffffffu, acc.x, o);
        acc.y += __shfl_xor_sync(0xffffffffu, acc.y, o);
        acc.z += __shfl_xor_sync(0xffffffffu, acc.z, o);
        acc.w += __shfl_xor_sync(0xffffffffu, acc.w, o);
    }

    if (lane < 4) {
        const float4 hwn = *(const float4*)(g_hw + (size_t)n * HID + q * 4);
        const float  di  = rsqrtf((float)(cnt + 1));
        const float4 cb4 = __ldg((const float4*)cb + q);
        float r0 = cb4.x + di * (acc.x + hwn.x);
        float r1 = cb4.y + di * (acc.y + hwn.y);
        float r2 = cb4.z + di * (acc.z + hwn.z);
        float r3 = cb4.w + di * (acc.w + hwn.w);

        if (!last) {
            *(float4*)(g_agg + (size_t)n * HID + q * 4) =
                make_float4(r0, r1, r2, r3);
        } else {
            float h0 = lrelu(r0), h1 = lrelu(r1), h2 = lrelu(r2), h3 = lrelu(r3);
            if (out_size >= (long long)NNODES * (1 + HID))
                *(float4*)(out + NNODES + (size_t)n * HID + q * 4) =
                    make_float4(h0, h1, h2, h3);

            const float4 pwa = __ldg((const float4*)pw + q * 2);
            const float4 pwb = __ldg((const float4*)pw + q * 2 + 1);
            float part = h0 * (pwa.x + pwa.y) + h1 * (pwa.z + pwa.w)
                       + h2 * (pwb.x + pwb.y) + h3 * (pwb.z + pwb.w);
            part += __shfl_xor_sync(0x0000000fu, part, 1);
            part += __shfl_xor_sync(0x0000000fu, part, 2);
            if (q == 0) out[n] = part + pb[0] + pb[1];
        }
    }
}

// ---------------- launch: fork-join across two streams ---------------------------
extern "C" void kernel_launch(void* const* d_in, const int* in_sizes, int n_in,
                              void* d_out, int out_size)
{
    const float *x = 0, *W1 = 0, *b1 = 0, *W2 = 0, *b2 = 0;
    const float *cw0 = 0, *cb0 = 0, *cw1 = 0, *cb1 = 0, *pw = 0, *pb = 0;
    const void  *edges = 0;
    long long    edge_elems = 0;

    int n256 = 0, n16 = 0;
    for (int i = 0; i < n_in; i++) {
        const long long sz = in_sizes[i];
        const void* p = d_in[i];
        switch (sz) {
            case 25600000LL: x  = (const float*)p; break;
            case 32768LL:    W1 = (const float*)p; break;
            case 4096LL:     W2 = (const float*)p; break;
            case 32LL:       pw = (const float*)p; break;
            case 2LL:        pb = (const float*)p; break;
            case 256LL:
                if      (n256 == 0) b1  = (const float*)p;
                else if (n256 == 1) cw0 = (const float*)p;
                else                cw1 = (const float*)p;
                n256++; break;
            case 16LL:
                if      (n16 == 0) b2  = (const float*)p;
                else if (n16 == 1) cb0 = (const float*)p;
                else               cb1 = (const float*)p;
                n16++; break;
            default:
                if (sz > 1000000LL) { edges = p; edge_elems = sz; }
                break;
        }
    }

    int E = (int)(edge_elems / 2);
    if (E > EMAX) E = EMAX;
    const int* srcp = (const int*)edges;
    const int* dstp = (const int*)edges + E;

    float* out = (float*)d_out;

    const int NB_NODES16 = NNODES / 16;
    const int HALF       = NNODES / 2;
    const int NB_HALF    = (HALF + 255) / 256;
    const int NB_EDGES   = (E + 255) / 256;
    const int NB_AGG     = NNODES / 8;   // 25000 exact

    static int inited = 0;
    static cudaStream_t s2 = 0;
    static cudaEvent_t  evRoot = 0, evCsr = 0;
    if (!inited) {
        cudaFuncSetAttribute(mlp_tc_kernel,
                             cudaFuncAttributeMaxDynamicSharedMemorySize,
                             SMEM_FLOATS * 4);
        cudaStreamCreateWithFlags(&s2, cudaStreamNonBlocking);
        cudaEventCreateWithFlags(&evRoot, cudaEventDisableTiming);
        cudaEventCreateWithFlags(&evCsr,  cudaEventDisableTiming);
        inited = 1;
    }

    // fork: s2 builds the bucket CSR while stream0 runs the MLP
    cudaEventRecord(evRoot, 0);
    cudaStreamWaitEvent(s2, evRoot, 0);

    zero_cnt_kernel<<<NB_HALF, 256, 0, s2>>>(0);
    zero_cnt_kernel<<<NB_HALF, 256, 0, s2>>>(HALF);
    scatter_kernel <<<NB_EDGES, 256, 0, s2>>>(srcp, dstp, E);
    cudaEventRecord(evCsr, s2);

    mlp_tc_kernel<<<NNODES / 64, 256, SMEM_FLOATS * 4>>>(x, W1, b1, W2, b2);   // launch 4

    cudaStreamWaitEvent(0, evCsr, 0);
    conv_pre_kernel<<<NB_NODES16, 256>>>(0, cw0);                               // launch 5
    agg_kernel<<<NB_AGG, 256>>>(cb0, pw, pb, out, (long long)out_size, 0);      // launch 6 (ncu)

    conv_pre_kernel<<<NB_NODES16, 256>>>(1, cw1);
    agg_kernel<<<NB_AGG, 256>>>(cb1, pw, pb, out, (long long)out_size, 1);
}